// round 1
// baseline (speedup 1.0000x reference)
#include <cuda_runtime.h>

#define NUM_USERS 100000
#define NUM_ITEMS 200000
#define NN        300000            // total nodes
#define EMB       64
#define VEC       (EMB / 4)         // 16 float4 per row
#define NNZ_E     2000000

// Ping-pong layer buffers (allocation-free rule: static __device__ scratch).
__device__ float4 g_bufA[(size_t)NN * VEC];
__device__ float4 g_bufB[(size_t)NN * VEC];

// ---------------------------------------------------------------------------
// init: ego0 = concat(user_emb, item_emb); acc(d_out) = ego0; bufA = ego0;
//       bufB = 0 (destination of layer-1 scatter).
// ---------------------------------------------------------------------------
__global__ void init_kernel(const float4* __restrict__ user,
                            const float4* __restrict__ item,
                            float4* __restrict__ out) {
    int i = blockIdx.x * blockDim.x + threadIdx.x;
    if (i >= NN * VEC) return;
    float4 v = (i < NUM_USERS * VEC) ? user[i] : item[i - NUM_USERS * VEC];
    out[i]     = v;
    g_bufA[i]  = v;
    g_bufB[i]  = make_float4(0.f, 0.f, 0.f, 0.f);
}

// ---------------------------------------------------------------------------
// SpMM scatter: 16 threads per edge, one float4 per thread.
// dst must be pre-zeroed. Uses vectorized red.global.add.v4.f32 (sm_90+).
// ---------------------------------------------------------------------------
__global__ void spmm_kernel(const float* __restrict__ vals,
                            const int*   __restrict__ rows,
                            const int*   __restrict__ cols,
                            const float4* __restrict__ src,
                            float4* __restrict__ dst) {
    int t  = blockIdx.x * blockDim.x + threadIdx.x;   // < 32M, fits in int
    int e  = t >> 4;
    int ln = t & 15;
    if (e >= NNZ_E) return;

    float v = __ldg(vals + e);
    int   r = __ldg(rows + e);
    int   c = __ldg(cols + e);

    float4 x = __ldg(src + (size_t)c * VEC + ln);
    float4 m = make_float4(v * x.x, v * x.y, v * x.z, v * x.w);

    float4* p = dst + (size_t)r * VEC + ln;
    asm volatile("red.global.add.v4.f32 [%0], {%1, %2, %3, %4};"
                 :: "l"(p), "f"(m.x), "f"(m.y), "f"(m.z), "f"(m.w)
                 : "memory");
}

// ---------------------------------------------------------------------------
// acc += layer_out (scaled); optionally zero the buffer that becomes the next
// scatter destination. Final call uses scale = 1/(N_LAYERS+1) and no zeroing.
// ---------------------------------------------------------------------------
__global__ void acc_zero_kernel(float4* __restrict__ acc,
                                const float4* __restrict__ layer_out,
                                float4* __restrict__ tozero,
                                float scale) {
    int i = blockIdx.x * blockDim.x + threadIdx.x;
    if (i >= NN * VEC) return;
    float4 a = acc[i];
    float4 s = layer_out[i];
    a.x = (a.x + s.x) * scale;
    a.y = (a.y + s.y) * scale;
    a.z = (a.z + s.z) * scale;
    a.w = (a.w + s.w) * scale;
    acc[i] = a;
    if (tozero) tozero[i] = make_float4(0.f, 0.f, 0.f, 0.f);
}

extern "C" void kernel_launch(void* const* d_in, const int* in_sizes, int n_in,
                              void* d_out, int out_size) {
    const float4* user = (const float4*)d_in[0];
    const float4* item = (const float4*)d_in[1];
    const float*  vals = (const float*)d_in[2];
    const int*    rows = (const int*)d_in[3];
    const int*    cols = (const int*)d_in[4];
    float4*       out  = (float4*)d_out;

    void *pa = nullptr, *pb = nullptr;
    cudaGetSymbolAddress(&pa, g_bufA);
    cudaGetSymbolAddress(&pb, g_bufB);
    float4* A = (float4*)pa;
    float4* B = (float4*)pb;

    const int T = 256;
    const int gridN    = (NN * VEC + T - 1) / T;        // 18750 blocks
    const int gridEdge = (NNZ_E * 16 + T - 1) / T;      // 125000 blocks

    // acc = ego0; A = ego0; B = 0
    init_kernel<<<gridN, T>>>(user, item, out);

    // layer 1: B = spmm(A);  acc += B;  A = 0
    spmm_kernel<<<gridEdge, T>>>(vals, rows, cols, A, B);
    acc_zero_kernel<<<gridN, T>>>(out, B, A, 1.0f);

    // layer 2: A = spmm(B);  acc += A;  B = 0
    spmm_kernel<<<gridEdge, T>>>(vals, rows, cols, B, A);
    acc_zero_kernel<<<gridN, T>>>(out, A, B, 1.0f);

    // layer 3: B = spmm(A);  acc = (acc + B) / 4
    spmm_kernel<<<gridEdge, T>>>(vals, rows, cols, A, B);
    acc_zero_kernel<<<gridN, T>>>(out, B, nullptr, 0.25f);
}

// round 4
// speedup vs baseline: 1.9427x; 1.9427x over previous
#include <cuda_runtime.h>

#define NUM_USERS 100000
#define NUM_ITEMS 200000
#define NN        300000
#define EMB       64
#define VEC       (EMB / 4)          // 16 float4 per row
#define NNZ_E     2000000

#define SCAN_T    256
#define SCAN_E    1024               // 4 elements per thread
#define SCAN_NB   ((NN + SCAN_E - 1) / SCAN_E)   // 293

// ---- static device scratch (allocation-free rule) ----
__device__ float4 g_e1[(size_t)NN * VEC];
__device__ float4 g_e2[(size_t)NN * VEC];
__device__ float4 g_e3[(size_t)NN * VEC];
__device__ int    g_rowptr[NN + 1];     // counts -> exclusive scan (in place)
__device__ int    g_cur[NN];            // scatter cursors
__device__ int2   g_edges[NNZ_E];       // {col, float_as_int(val)} bucketed by row
__device__ int    g_blksum[SCAN_NB];

// ---------------------------------------------------------------------------
__global__ void zero_rowptr_kernel() {
    int i = blockIdx.x * blockDim.x + threadIdx.x;
    if (i <= NN) g_rowptr[i] = 0;
}

__global__ void hist_kernel(const int* __restrict__ rows) {
    int e = blockIdx.x * blockDim.x + threadIdx.x;
    if (e < NNZ_E) atomicAdd(&g_rowptr[__ldg(rows + e)], 1);
}

// Block-local exclusive scan (4 elems/thread), in place on g_rowptr; block sums out.
__global__ void scan1_kernel() {
    __shared__ int sh[SCAN_T];
    int b = blockIdx.x, t = threadIdx.x;
    int base = b * SCAN_E + t * 4;
    int v[4]; int s = 0;
#pragma unroll
    for (int k = 0; k < 4; k++) {
        int idx = base + k;
        v[k] = (idx < NN) ? g_rowptr[idx] : 0;
        s += v[k];
    }
    sh[t] = s; __syncthreads();
    for (int off = 1; off < SCAN_T; off <<= 1) {
        int x = (t >= off) ? sh[t - off] : 0;
        __syncthreads();
        sh[t] += x;
        __syncthreads();
    }
    if (t == SCAN_T - 1) g_blksum[b] = sh[t];
    int run = sh[t] - s;                 // exclusive prefix for this thread
#pragma unroll
    for (int k = 0; k < 4; k++) {
        int idx = base + k;
        if (idx < NN) g_rowptr[idx] = run;
        run += v[k];
    }
}

// Single-block exclusive scan of SCAN_NB block sums.
__global__ void scan2_kernel() {
    __shared__ int sh[512];
    int t = threadIdx.x;
    int v = (t < SCAN_NB) ? g_blksum[t] : 0;
    sh[t] = v; __syncthreads();
    for (int off = 1; off < 512; off <<= 1) {
        int x = (t >= off) ? sh[t - off] : 0;
        __syncthreads();
        sh[t] += x;
        __syncthreads();
    }
    if (t < SCAN_NB) g_blksum[t] = sh[t] - v;
}

// Add block offsets; init cursors; terminate rowptr.
__global__ void scan3_kernel() {
    int i = blockIdx.x * blockDim.x + threadIdx.x;
    if (i < NN) {
        int r = g_rowptr[i] + g_blksum[i / SCAN_E];
        g_rowptr[i] = r;
        g_cur[i]    = r;
    }
    if (i == 0) g_rowptr[NN] = NNZ_E;
}

__global__ void bucket_kernel(const float* __restrict__ vals,
                              const int*   __restrict__ rows,
                              const int*   __restrict__ cols) {
    int e = blockIdx.x * blockDim.x + threadIdx.x;
    if (e >= NNZ_E) return;
    int r   = __ldg(rows + e);
    int pos = atomicAdd(&g_cur[r], 1);
    g_edges[pos] = make_int2(__ldg(cols + e), __float_as_int(__ldg(vals + e)));
}

// ---------------------------------------------------------------------------
// CSR SpMM: 16 threads per row, register accumulation, streaming store.
// FIRST layer gathers from the two input embedding tables directly.
// ---------------------------------------------------------------------------
template <bool FIRST>
__global__ void __launch_bounds__(256)
spmm_csr_kernel(const float4* __restrict__ src,
                const float4* __restrict__ user,
                const float4* __restrict__ item,
                float4* __restrict__ dst) {
    int t  = blockIdx.x * blockDim.x + threadIdx.x;
    int r  = t >> 4;
    int ln = t & 15;
    if (r >= NN) return;

    int s = __ldg(&g_rowptr[r]);
    int e = __ldg(&g_rowptr[r + 1]);

    float4 acc = make_float4(0.f, 0.f, 0.f, 0.f);
    for (int k = s; k < e; k++) {
        int2  ed = __ldg(&g_edges[k]);
        int   c  = ed.x;
        float v  = __int_as_float(ed.y);
        float4 x;
        if (FIRST)
            x = (c < NUM_USERS) ? __ldg(user + c * VEC + ln)
                                : __ldg(item + (c - NUM_USERS) * VEC + ln);
        else
            x = __ldg(src + c * VEC + ln);
        acc.x += v * x.x; acc.y += v * x.y; acc.z += v * x.z; acc.w += v * x.w;
    }
    __stcs(dst + (size_t)r * VEC + ln, acc);   // evict-first: keep src in L2
}

// out = (e0 + e1 + e2 + e3) / 4
__global__ void final_kernel(const float4* __restrict__ user,
                             const float4* __restrict__ item,
                             float4* __restrict__ out) {
    int i = blockIdx.x * blockDim.x + threadIdx.x;
    if (i >= NN * VEC) return;
    float4 e0 = (i < NUM_USERS * VEC) ? __ldg(user + i) : __ldg(item + i - NUM_USERS * VEC);
    float4 a = g_e1[i], b = g_e2[i], c = g_e3[i];
    float4 o;
    o.x = (e0.x + a.x + b.x + c.x) * 0.25f;
    o.y = (e0.y + a.y + b.y + c.y) * 0.25f;
    o.z = (e0.z + a.z + b.z + c.z) * 0.25f;
    o.w = (e0.w + a.w + b.w + c.w) * 0.25f;
    out[i] = o;
}

// ---------------------------------------------------------------------------
extern "C" void kernel_launch(void* const* d_in, const int* in_sizes, int n_in,
                              void* d_out, int out_size) {
    const float4* user = (const float4*)d_in[0];
    const float4* item = (const float4*)d_in[1];
    const float*  vals = (const float*)d_in[2];
    const int*    rows = (const int*)d_in[3];
    const int*    cols = (const int*)d_in[4];
    float4*       out  = (float4*)d_out;

    void *p1, *p2, *p3;
    cudaGetSymbolAddress(&p1, g_e1);
    cudaGetSymbolAddress(&p2, g_e2);
    cudaGetSymbolAddress(&p3, g_e3);
    float4* E1 = (float4*)p1;
    float4* E2 = (float4*)p2;
    float4* E3 = (float4*)p3;

    const int T = 256;
    const int gZero = (NN + 1 + T - 1) / T;
    const int gEdge = (NNZ_E + T - 1) / T;
    const int gScan3 = (NN + T - 1) / T;
    const int gRow  = (NN * VEC + T - 1) / T;   // 18750

    // --- CSR build ---
    zero_rowptr_kernel<<<gZero, T>>>();
    hist_kernel<<<gEdge, T>>>(rows);
    scan1_kernel<<<SCAN_NB, SCAN_T>>>();
    scan2_kernel<<<1, 512>>>();
    scan3_kernel<<<gScan3, T>>>();
    bucket_kernel<<<gEdge, T>>>(vals, rows, cols);

    // --- 3 propagation layers ---
    spmm_csr_kernel<true ><<<gRow, T>>>(nullptr, user, item, E1);
    spmm_csr_kernel<false><<<gRow, T>>>(E1, nullptr, nullptr, E2);
    spmm_csr_kernel<false><<<gRow, T>>>(E2, nullptr, nullptr, E3);

    // --- fused accumulate + normalize ---
    final_kernel<<<gRow, T>>>(user, item, out);
}